// round 12
// baseline (speedup 1.0000x reference)
#include <cuda_runtime.h>
#include <cuda_bf16.h>
#include <cstdint>

#define NUM_M 8
#define DD 256
#define HH 256
#define BM 64
#define NT 512

#define TGT_STRIDE 264   // bf16 elems per row; word-stride 132 -> conflict-free epilogue reads

// ---- dynamic smem layout (bytes) ----
#define OFF_B     0                          // 4 ktiles x [256 rows x 128B] = 131072 (W bf16, resident)
#define OFF_A     131072                     // single A buffer (32768)
#define OFF_TGT   163840                     // 64 x 264 bf16 = 33792
#define OFF_BIAS  197632                     // 256 f32
#define OFF_TN    198656                     // 64 f32
#define OFF_LOGIT 198912                     // 8 x 64 f32
#define OFF_RNUM  200960                     // 64 x 8 f32
#define OFF_RSQ   203008                     // 64 x 8 f32
#define OFF_ATTP  205056                     // prev-tile attention [8][64] f32 = 2048
#define SMEM_SIZE 207104

#define SWZ(o) ((o) ^ (((o) >> 3) & 0x70))

__device__ __forceinline__ uint32_t smem_to_u32(const void* p) {
    uint32_t a;
    asm("{ .reg .u64 t; cvta.to.shared.u64 t, %1; cvt.u32.u64 %0, t; }" : "=r"(a) : "l"(p));
    return a;
}
__device__ __forceinline__ float fast_tanh(float x) {
    float y; asm("tanh.approx.f32 %0, %1;" : "=f"(y) : "f"(x)); return y;
}
__device__ __forceinline__ uint32_t pack_bf16x2(float lo, float hi) {
    uint32_t r; asm("cvt.rn.bf16x2.f32 %0, %1, %2;" : "=r"(r) : "f"(hi), "f"(lo)); return r;
}

#define LDSM4(r, addr) \
    asm volatile("ldmatrix.sync.aligned.m8n8.x4.shared.b16 {%0,%1,%2,%3}, [%4];" \
        : "=r"((r)[0]), "=r"((r)[1]), "=r"((r)[2]), "=r"((r)[3]) : "r"(addr))

#define MMA_BF16(c, a, bv0, bv1) \
    asm volatile("mma.sync.aligned.m16n8k16.row.col.f32.bf16.bf16.f32 " \
        "{%0,%1,%2,%3}, {%4,%5,%6,%7}, {%8,%9}, {%0,%1,%2,%3};" \
        : "+f"((c)[0]), "+f"((c)[1]), "+f"((c)[2]), "+f"((c)[3]) \
        : "r"((a)[0]), "r"((a)[1]), "r"((a)[2]), "r"((a)[3]), "r"(bv0), "r"(bv1))

// ---- linear-granule A prefetch: granule g = wid*256 + j*32 + lane ----
__device__ __forceinline__ void loadA_regs(uint2* pf, const float* __restrict__ homo,
                                           int m, int N, int n0, int nv,
                                           int wid, int lane) {
    const float4* base = reinterpret_cast<const float4*>(homo)
                         + ((size_t)m * N + n0) * (DD / 4);
    const int g0 = wid * 256 + lane;
    #pragma unroll
    for (int j = 0; j < 8; ++j) {
        int g = g0 + j * 32;
        float4 v = make_float4(0.f, 0.f, 0.f, 0.f);
        if ((g >> 6) < nv) v = base[g];
        pf[j].x = pack_bf16x2(v.x, v.y);
        pf[j].y = pack_bf16x2(v.z, v.w);
    }
}

__device__ __forceinline__ void storeA(const uint2* pf, char* smem, int wid, int lane) {
    const int g0 = wid * 256 + lane;
    #pragma unroll
    for (int j = 0; j < 8; ++j) {
        int g    = g0 + j * 32;
        int row  = g >> 6;
        int c4   = g & 63;
        int kt   = c4 >> 4;
        uint32_t off = SWZ((uint32_t)(row * 128 + (c4 & 15) * 8));
        *reinterpret_cast<uint2*>(smem + OFF_A + kt * 8192 + off) = pf[j];
    }
}

__global__ __launch_bounds__(NT, 1)
void hete_mma_kernel(const int*   __restrict__ nodes,
                     const float* __restrict__ homo,   // [M, N, D] f32
                     const float* __restrict__ W,      // [H, D] f32
                     const float* __restrict__ bvec,   // [H]
                     const float* __restrict__ oe,     // [NODE_NUM, H]
                     float*       __restrict__ out,    // [N, D]
                     int N)
{
    extern __shared__ char smem[];
    const uint32_t sb = smem_to_u32(smem);
    const int tid  = threadIdx.x;
    const int lane = tid & 31;
    const int wid  = tid >> 5;
    const int wm   = wid & 1;    // warp row group: rows wm*32 .. +31
    const int wn   = wid >> 1;   // warp col group: cols wn*32 .. +31

    float* sbias  = (float*)(smem + OFF_BIAS);
    float* stn    = (float*)(smem + OFF_TN);
    float* slogit = (float*)(smem + OFF_LOGIT);
    float* srnum  = (float*)(smem + OFF_RNUM);   // [64][8]
    float* srsq   = (float*)(smem + OFF_RSQ);    // [64][8]
    float* sattp  = (float*)(smem + OFF_ATTP);   // [8][64] prev-tile attention

    const int gid = lane >> 2;
    const int tig = lane & 3;
    const int rowsel = lane & 15;
    const uint32_t kbsel = (uint32_t)((lane >> 4) << 4);
    const __nv_bfloat162* tg2 = reinterpret_cast<const __nv_bfloat162*>(smem + OFF_TGT);

    uint32_t aOff[2], bOff[2];
    #pragma unroll
    for (int mt = 0; mt < 2; ++mt)
        aOff[mt] = (uint32_t)((wm * 32 + mt * 16 + rowsel) * 128);
    #pragma unroll
    for (int np = 0; np < 2; ++np)
        bOff[np] = (uint32_t)((wn * 32 + np * 16 + rowsel) * 128);

    // slice geometry (deferred phase-3): thread owns (row, float4-col)
    const int srow = tid >> 3;          // 0..63
    const int sc4b = tid & 7;           // base float4 col, slice m adds m*8

    // ---- one-time init: W -> bf16 resident B, bias ----
    if (tid < HH) sbias[tid] = bvec[tid];
    for (int q = tid; q < HH * (DD / 4); q += NT) {
        int h  = q >> 6;
        int c4 = q & 63;
        float4 v = reinterpret_cast<const float4*>(W)[(size_t)h * (DD / 4) + c4];
        int ktile = c4 >> 4;
        uint32_t off = SWZ((uint32_t)(h * 128 + (c4 & 15) * 8));
        uint2 p;
        p.x = pack_bf16x2(v.x, v.y);
        p.y = pack_bf16x2(v.z, v.w);
        *reinterpret_cast<uint2*>(smem + OFF_B + ktile * 32768 + off) = p;
    }

    const int numTiles = (N + BM - 1) / BM;
    int prevN0 = 0, prevNv = 0;
    bool prevValid = false;

    // ======================= persistent tile loop =======================
    for (int tile = blockIdx.x; tile < numTiles; tile += gridDim.x) {
        const int n0 = tile * BM;
        const int nv = min(BM, N - n0);

        // ---- gather tgt rows -> bf16 (prev tile done with TGT/A at its last bar) ----
        for (int q = tid; q < BM * (HH / 4); q += NT) {
            int r  = q >> 6;
            int c4 = q & 63;
            int rr = (r < nv) ? r : (nv - 1);
            int row = nodes[n0 + rr];
            float4 v = reinterpret_cast<const float4*>(oe)[(size_t)row * (HH / 4) + c4];
            uint2 p;
            p.x = pack_bf16x2(v.x, v.y);
            p.y = pack_bf16x2(v.z, v.w);
            *reinterpret_cast<uint2*>(smem + OFF_TGT + (size_t)r * (TGT_STRIDE * 2) + c4 * 8) = p;
        }

        // A for m=0
        uint2 pf[8];
        loadA_regs(pf, homo, 0, N, n0, nv, wid, lane);
        storeA(pf, smem, wid, lane);
        __syncthreads();   // TGT + A[0] (+ B/bias on first iter) visible

        // tn (2 threads per row); done before first logit tail (bar1 of m=0)
        if (tid < 2 * BM) {
            int r = tid >> 1, part = tid & 1;
            const __nv_bfloat162* trow = reinterpret_cast<const __nv_bfloat162*>(
                smem + OFF_TGT + (size_t)r * (TGT_STRIDE * 2)) + part * 64;
            float acc = 0.f;
            #pragma unroll 16
            for (int c = 0; c < 64; ++c) {
                float2 t = __bfloat1622float2(trow[c]);
                acc = fmaf(t.x, t.x, acc);
                acc = fmaf(t.y, t.y, acc);
            }
            acc += __shfl_xor_sync(0xffffffffu, acc, 1);
            if (part == 0) stn[r] = fmaxf(sqrtf(acc), 1e-8f);
        }

        // ---------------- meta-path loop (R5 body + phase-3 slices) ----------------
        for (int m = 0; m < NUM_M; ++m) {
            float acc[2][4][4];
            #pragma unroll
            for (int mt = 0; mt < 2; ++mt)
                #pragma unroll
                for (int nt = 0; nt < 4; ++nt)
                    #pragma unroll
                    for (int e = 0; e < 4; ++e) acc[mt][nt][e] = 0.f;

            // register double-buffered LDSM pipeline over 16 k-steps
            uint32_t a[2][2][4], b[2][2][4];
            {
                #pragma unroll
                for (int mt = 0; mt < 2; ++mt) LDSM4(a[0][mt], sb + OFF_A + SWZ(aOff[mt] + kbsel));
                #pragma unroll
                for (int np = 0; np < 2; ++np) LDSM4(b[0][np], sb + OFF_B + SWZ(bOff[np] + kbsel));
            }
            #pragma unroll
            for (int ks = 0; ks < 16; ++ks) {
                const int c2 = ks & 1;
                if (ks < 15) {
                    const int nks = ks + 1;
                    const uint32_t kb = (uint32_t)((nks & 3) * 32) + kbsel;
                    const uint32_t aB = sb + OFF_A + (nks >> 2) * 8192;
                    const uint32_t bB = sb + OFF_B + (nks >> 2) * 32768;
                    #pragma unroll
                    for (int mt = 0; mt < 2; ++mt) LDSM4(a[nks & 1][mt], aB + SWZ(aOff[mt] + kb));
                    #pragma unroll
                    for (int np = 0; np < 2; ++np) LDSM4(b[nks & 1][np], bB + SWZ(bOff[np] + kb));
                }
                #pragma unroll
                for (int mt = 0; mt < 2; ++mt)
                    #pragma unroll
                    for (int nt = 0; nt < 4; ++nt) {
                        const int np = nt >> 1, hl = nt & 1;
                        MMA_BF16(acc[mt][nt], a[c2][mt], b[c2][np][hl], b[c2][np][hl + 2]);
                    }
            }

            // prefetch next meta-path's A (hides DRAM behind epilogue)
            if (m + 1 < NUM_M) loadA_regs(pf, homo, m + 1, N, n0, nv, wid, lane);

            // ---- epilogue: bias + tanh + dot(tgt) + sqnorm (consumes acc) ----
            float numr[2][2], sqr[2][2];
            #pragma unroll
            for (int mt = 0; mt < 2; ++mt)
                #pragma unroll
                for (int h = 0; h < 2; ++h) { numr[mt][h] = 0.f; sqr[mt][h] = 0.f; }

            #pragma unroll
            for (int mt = 0; mt < 2; ++mt) {
                const int rowA = wm * 32 + mt * 16 + gid;
                const int rowB = rowA + 8;
                #pragma unroll
                for (int nt = 0; nt < 4; ++nt) {
                    const int col = wn * 32 + nt * 8 + tig * 2;
                    float2 b2 = *reinterpret_cast<const float2*>(&sbias[col]);
                    float2 tA = __bfloat1622float2(tg2[rowA * (TGT_STRIDE / 2) + (col >> 1)]);
                    float2 tB = __bfloat1622float2(tg2[rowB * (TGT_STRIDE / 2) + (col >> 1)]);
                    float h0 = fast_tanh(acc[mt][nt][0] + b2.x);
                    float h1 = fast_tanh(acc[mt][nt][1] + b2.y);
                    float h2 = fast_tanh(acc[mt][nt][2] + b2.x);
                    float h3 = fast_tanh(acc[mt][nt][3] + b2.y);
                    numr[mt][0] = fmaf(h0, tA.x, numr[mt][0]);
                    numr[mt][0] = fmaf(h1, tA.y, numr[mt][0]);
                    sqr[mt][0]  = fmaf(h0, h0, sqr[mt][0]);
                    sqr[mt][0]  = fmaf(h1, h1, sqr[mt][0]);
                    numr[mt][1] = fmaf(h2, tB.x, numr[mt][1]);
                    numr[mt][1] = fmaf(h3, tB.y, numr[mt][1]);
                    sqr[mt][1]  = fmaf(h2, h2, sqr[mt][1]);
                    sqr[mt][1]  = fmaf(h3, h3, sqr[mt][1]);
                }
            }

            // ---- slice-j of PREVIOUS tile's weighted sum: issue loads now
            // (acc registers are dead -> sv reuses that space) ----
            const bool sval = prevValid && (srow < prevNv);
            float4 sv[8];
            if (sval) {
                const int sc4 = sc4b + m * 8;
                #pragma unroll
                for (int mm = 0; mm < NUM_M; ++mm)
                    sv[mm] = reinterpret_cast<const float4*>(homo)
                                 [((size_t)mm * N + prevN0 + srow) * (DD / 4) + sc4];
            }

            // cross-lane reduction (covers slice-load latency)
            #pragma unroll
            for (int mt = 0; mt < 2; ++mt)
                #pragma unroll
                for (int h = 0; h < 2; ++h) {
                    numr[mt][h] += __shfl_xor_sync(0xffffffffu, numr[mt][h], 1);
                    numr[mt][h] += __shfl_xor_sync(0xffffffffu, numr[mt][h], 2);
                    sqr[mt][h]  += __shfl_xor_sync(0xffffffffu, sqr[mt][h], 1);
                    sqr[mt][h]  += __shfl_xor_sync(0xffffffffu, sqr[mt][h], 2);
                }
            if (tig == 0) {
                #pragma unroll
                for (int mt = 0; mt < 2; ++mt)
                    #pragma unroll
                    for (int h = 0; h < 2; ++h) {
                        int row = wm * 32 + mt * 16 + h * 8 + gid;
                        srnum[row * 8 + wn] = numr[mt][h];
                        srsq[row * 8 + wn]  = sqr[mt][h];
                    }
            }

            // consume slice: attention-weighted accumulate + store
            if (sval) {
                const int sc4 = sc4b + m * 8;
                float4 o = make_float4(0.f, 0.f, 0.f, 0.f);
                #pragma unroll
                for (int mm = 0; mm < NUM_M; ++mm) {
                    float aw = sattp[mm * BM + srow];
                    o.x = fmaf(aw, sv[mm].x, o.x);
                    o.y = fmaf(aw, sv[mm].y, o.y);
                    o.z = fmaf(aw, sv[mm].z, o.z);
                    o.w = fmaf(aw, sv[mm].w, o.w);
                }
                reinterpret_cast<float4*>(out)[((size_t)prevN0 + srow) * (DD / 4) + sc4] = o;
            }

            __syncthreads();   // bar1: A reads done, partials visible

            if (m + 1 < NUM_M) storeA(pf, smem, wid, lane);
            if (tid < BM) {
                float num = 0.f, sq = 0.f;
                #pragma unroll
                for (int w = 0; w < 8; ++w) {
                    num += srnum[tid * 8 + w];
                    sq  += srsq[tid * 8 + w];
                }
                float hn = fmaxf(sqrtf(sq), 1e-8f);
                slogit[m * BM + tid] = num / (hn * stn[tid]);
            }
            __syncthreads();   // bar2: new A visible, partial arrays free
        }

        // ---- softmax -> attPrev (same threads that wrote slogit; no bar needed) ----
        if (tid < BM) {
            float mx = -1e30f;
            #pragma unroll
            for (int m = 0; m < NUM_M; ++m) mx = fmaxf(mx, slogit[m * BM + tid]);
            float e[NUM_M], sum = 0.f;
            #pragma unroll
            for (int m = 0; m < NUM_M; ++m) {
                e[m] = __expf(slogit[m * BM + tid] - mx);
                sum += e[m];
            }
            float inv = 1.f / sum;
            #pragma unroll
            for (int m = 0; m < NUM_M; ++m) sattp[m * BM + tid] = e[m] * inv;
        }
        prevN0 = n0;
        prevNv = nv;
        prevValid = true;
        // attPrev consumed starting next tile's m-loop, after its init barrier
    }

    // ---- drain: full weighted sum for the last tile ----
    __syncthreads();
    if (prevValid) {
        for (int q = tid; q < BM * (DD / 4); q += NT) {
            int r  = q >> 6;
            int c4 = q & 63;
            if (r < prevNv) {
                float4 o = make_float4(0.f, 0.f, 0.f, 0.f);
                #pragma unroll
                for (int m = 0; m < NUM_M; ++m) {
                    float aw = sattp[m * BM + r];
                    float4 v = reinterpret_cast<const float4*>(homo)
                                   [((size_t)m * N + prevN0 + r) * (DD / 4) + c4];
                    o.x = fmaf(aw, v.x, o.x);
                    o.y = fmaf(aw, v.y, o.y);
                    o.z = fmaf(aw, v.z, o.z);
                    o.w = fmaf(aw, v.w, o.w);
                }
                reinterpret_cast<float4*>(out)[(size_t)(prevN0 + r) * (DD / 4) + c4] = o;
            }
        }
    }
}

extern "C" void kernel_launch(void* const* d_in, const int* in_sizes, int n_in,
                              void* d_out, int out_size) {
    const int*   nodes = (const int*)  d_in[0];
    const float* homo  = (const float*)d_in[1];
    const float* W     = (const float*)d_in[2];
    const float* b     = (const float*)d_in[3];
    const float* oe    = (const float*)d_in[4];
    float* out = (float*)d_out;
    const int N = in_sizes[0];
    (void)n_in; (void)out_size;

    cudaFuncSetAttribute(hete_mma_kernel,
                         cudaFuncAttributeMaxDynamicSharedMemorySize, SMEM_SIZE);

    int dev = 0, sms = 148;
    cudaGetDevice(&dev);
    cudaDeviceGetAttribute(&sms, cudaDevAttrMultiProcessorCount, dev);

    int tiles = (N + BM - 1) / BM;
    int grid = tiles < sms ? tiles : sms;
    hete_mma_kernel<<<grid, NT, SMEM_SIZE>>>(nodes, homo, W, b, oe, out, N);
}

// round 13
// speedup vs baseline: 1.0616x; 1.0616x over previous
#include <cuda_runtime.h>
#include <cuda_bf16.h>
#include <cstdint>

#define NUM_M 8
#define DD 256
#define HH 256
#define BM 64
#define NT 512

#define TGT_STRIDE 264   // bf16 elems per row; word-stride 132 -> conflict-free epilogue reads

// ---- dynamic smem layout (bytes) ----
#define OFF_B     0                          // 4 ktiles x [256 rows x 128B] = 131072 (W bf16, resident)
#define OFF_A0    131072                     // A buffer 0 (32768)  -- single buffer used (R5 scheme)
#define OFF_TGT   163840                     // 64 x 264 bf16 = 33792
#define OFF_BIAS  197632                     // 256 f32
#define OFF_TN    198656                     // 64 f32
#define OFF_LOGIT 198912                     // 8 x 64 f32
#define OFF_RNUM  200960                     // 64 x 8 f32
#define OFF_RSQ   203008                     // 64 x 8 f32
#define SMEM_SIZE 205056                     // ~200 KB

#define SWZ(o) ((o) ^ (((o) >> 3) & 0x70))

__device__ __forceinline__ uint32_t smem_to_u32(const void* p) {
    uint32_t a;
    asm("{ .reg .u64 t; cvta.to.shared.u64 t, %1; cvt.u32.u64 %0, t; }" : "=r"(a) : "l"(p));
    return a;
}
__device__ __forceinline__ float fast_tanh(float x) {
    float y; asm("tanh.approx.f32 %0, %1;" : "=f"(y) : "f"(x)); return y;
}
__device__ __forceinline__ uint32_t pack_bf16x2(float lo, float hi) {
    uint32_t r; asm("cvt.rn.bf16x2.f32 %0, %1, %2;" : "=r"(r) : "f"(hi), "f"(lo)); return r;
}

#define LDSM4(r, addr) \
    asm volatile("ldmatrix.sync.aligned.m8n8.x4.shared.b16 {%0,%1,%2,%3}, [%4];" \
        : "=r"((r)[0]), "=r"((r)[1]), "=r"((r)[2]), "=r"((r)[3]) : "r"(addr))

#define MMA_BF16(c, a, bv0, bv1) \
    asm volatile("mma.sync.aligned.m16n8k16.row.col.f32.bf16.bf16.f32 " \
        "{%0,%1,%2,%3}, {%4,%5,%6,%7}, {%8,%9}, {%0,%1,%2,%3};" \
        : "+f"((c)[0]), "+f"((c)[1]), "+f"((c)[2]), "+f"((c)[3]) \
        : "r"((a)[0]), "r"((a)[1]), "r"((a)[2]), "r"((a)[3]), "r"(bv0), "r"(bv1))

// ---- linear-granule A prefetch: granule g = wid*256 + j*32 + lane ----
__device__ __forceinline__ void loadA_regs(uint2* pf, const float* __restrict__ homo,
                                           int m, int N, int n0, int nv,
                                           int wid, int lane) {
    const float4* base = reinterpret_cast<const float4*>(homo)
                         + ((size_t)m * N + n0) * (DD / 4);
    const int g0 = wid * 256 + lane;
    #pragma unroll
    for (int j = 0; j < 8; ++j) {
        int g = g0 + j * 32;
        float4 v = make_float4(0.f, 0.f, 0.f, 0.f);
        if ((g >> 6) < nv) v = base[g];
        pf[j].x = pack_bf16x2(v.x, v.y);
        pf[j].y = pack_bf16x2(v.z, v.w);
    }
}

__device__ __forceinline__ void storeA(const uint2* pf, char* smem, int wid, int lane) {
    const int g0 = wid * 256 + lane;
    #pragma unroll
    for (int j = 0; j < 8; ++j) {
        int g    = g0 + j * 32;
        int row  = g >> 6;
        int c4   = g & 63;
        int kt   = c4 >> 4;
        uint32_t off = SWZ((uint32_t)(row * 128 + (c4 & 15) * 8));
        *reinterpret_cast<uint2*>(smem + OFF_A0 + kt * 8192 + off) = pf[j];
    }
}

__global__ __launch_bounds__(NT, 1)
void hete_mma_kernel(const int*   __restrict__ nodes,
                     const float* __restrict__ homo,   // [M, N, D] f32
                     const float* __restrict__ W,      // [H, D] f32
                     const float* __restrict__ bvec,   // [H]
                     const float* __restrict__ oe,     // [NODE_NUM, H]
                     float*       __restrict__ out,    // [N, D]
                     int N)
{
    extern __shared__ char smem[];
    const uint32_t sb = smem_to_u32(smem);
    const int tid  = threadIdx.x;
    const int lane = tid & 31;
    const int wid  = tid >> 5;
    const int wm   = wid & 1;    // warp row group: rows wm*32 .. +31
    const int wn   = wid >> 1;   // warp col group: cols wn*32 .. +31
    const int n0   = blockIdx.x * BM;
    const int nv   = min(BM, N - n0);

    float* sbias  = (float*)(smem + OFF_BIAS);
    float* stn    = (float*)(smem + OFF_TN);
    float* slogit = (float*)(smem + OFF_LOGIT);
    float* srnum  = (float*)(smem + OFF_RNUM);   // [64][8]
    float* srsq   = (float*)(smem + OFF_RSQ);    // [64][8]

    // ---------------- init phase ----------------
    if (tid < HH) sbias[tid] = bvec[tid];

    // gather tgt rows -> bf16 (row stride 264 bf16)
    for (int q = tid; q < BM * (HH / 4); q += NT) {
        int r  = q >> 6;
        int c4 = q & 63;
        int rr = (r < nv) ? r : (nv - 1);
        int row = nodes[n0 + rr];
        float4 v = reinterpret_cast<const float4*>(oe)[(size_t)row * (HH / 4) + c4];
        uint2 p;
        p.x = pack_bf16x2(v.x, v.y);
        p.y = pack_bf16x2(v.z, v.w);
        *reinterpret_cast<uint2*>(smem + OFF_TGT + (size_t)r * (TGT_STRIDE * 2) + c4 * 8) = p;
    }

    // W -> bf16 resident B: 4 k-tile blocks of [256 rows x 128B], SW128 swizzle
    for (int q = tid; q < HH * (DD / 4); q += NT) {
        int h  = q >> 6;
        int c4 = q & 63;
        float4 v = reinterpret_cast<const float4*>(W)[(size_t)h * (DD / 4) + c4];
        int ktile = c4 >> 4;
        uint32_t off = SWZ((uint32_t)(h * 128 + (c4 & 15) * 8));
        uint2 p;
        p.x = pack_bf16x2(v.x, v.y);
        p.y = pack_bf16x2(v.z, v.w);
        *reinterpret_cast<uint2*>(smem + OFF_B + ktile * 32768 + off) = p;
    }

    // A for m=0
    {
        uint2 pf0[8];
        loadA_regs(pf0, homo, 0, N, n0, nv, wid, lane);
        storeA(pf0, smem, wid, lane);
    }
    __syncthreads();

    // tn from bf16 tgt (2 threads per row)
    if (tid < 2 * BM) {
        int r = tid >> 1, part = tid & 1;
        const __nv_bfloat162* trow = reinterpret_cast<const __nv_bfloat162*>(
            smem + OFF_TGT + (size_t)r * (TGT_STRIDE * 2)) + part * 64;
        float acc = 0.f;
        #pragma unroll 16
        for (int c = 0; c < 64; ++c) {
            float2 t = __bfloat1622float2(trow[c]);
            acc = fmaf(t.x, t.x, acc);
            acc = fmaf(t.y, t.y, acc);
        }
        acc += __shfl_xor_sync(0xffffffffu, acc, 1);
        if (part == 0) stn[r] = fmaxf(sqrtf(acc), 1e-8f);
    }

    const int gid = lane >> 2;
    const int tig = lane & 3;
    const int rowsel = lane & 15;
    const uint32_t kbsel = (uint32_t)((lane >> 4) << 4);
    const __nv_bfloat162* tg2 = reinterpret_cast<const __nv_bfloat162*>(smem + OFF_TGT);

    // ---- XOR-folded LDSM addressing ----
    // SWZ(row*128 + kb) = row*128 ^ ((row&7)<<4) ^ kb   (kb < 128, fields disjoint)
    // kb = kbsel | kk32  ->  precompute pre = row*128 ^ ((row&7)<<4) ^ kbsel,
    // per k-step the address is  base + ktile*stride + (pre ^ kk32), kk32 immediate.
    const uint32_t sbA = sb + OFF_A0;
    const uint32_t sbB = sb + OFF_B;
    uint32_t preA[2], preB[2];
    #pragma unroll
    for (int mt = 0; mt < 2; ++mt) {
        uint32_t row = (uint32_t)(wm * 32 + mt * 16 + rowsel);
        preA[mt] = (row * 128) ^ ((row & 7) << 4) ^ kbsel;
    }
    #pragma unroll
    for (int np = 0; np < 2; ++np) {
        uint32_t row = (uint32_t)(wn * 32 + np * 16 + rowsel);
        preB[np] = (row * 128) ^ ((row & 7) << 4) ^ kbsel;
    }

    // ---------------- meta-path loop (R5 schedule) ----------------
    for (int m = 0; m < NUM_M; ++m) {
        float acc[2][4][4];
        #pragma unroll
        for (int mt = 0; mt < 2; ++mt)
            #pragma unroll
            for (int nt = 0; nt < 4; ++nt)
                #pragma unroll
                for (int e = 0; e < 4; ++e) acc[mt][nt][e] = 0.f;

        // register double-buffered LDSM pipeline over 16 k-steps
        uint32_t a[2][2][4], b[2][2][4];
        {
            #pragma unroll
            for (int mt = 0; mt < 2; ++mt) LDSM4(a[0][mt], sbA + preA[mt]);
            #pragma unroll
            for (int np = 0; np < 2; ++np) LDSM4(b[0][np], sbB + preB[np]);
        }
        #pragma unroll
        for (int ks = 0; ks < 16; ++ks) {
            const int c2 = ks & 1;
            if (ks < 15) {
                const int nks = ks + 1;
                const uint32_t kk32 = (uint32_t)((nks & 3) * 32);   // immediate
                const uint32_t aOfs = (uint32_t)((nks >> 2) * 8192);
                const uint32_t bOfs = (uint32_t)((nks >> 2) * 32768);
                #pragma unroll
                for (int mt = 0; mt < 2; ++mt)
                    LDSM4(a[nks & 1][mt], sbA + aOfs + (preA[mt] ^ kk32));
                #pragma unroll
                for (int np = 0; np < 2; ++np)
                    LDSM4(b[nks & 1][np], sbB + bOfs + (preB[np] ^ kk32));
            }
            #pragma unroll
            for (int mt = 0; mt < 2; ++mt)
                #pragma unroll
                for (int nt = 0; nt < 4; ++nt) {
                    const int np = nt >> 1, hl = nt & 1;
                    MMA_BF16(acc[mt][nt], a[c2][mt], b[c2][np][hl], b[c2][np][hl + 2]);
                }
        }

        // prefetch next meta-path's A (coalesced) to hide DRAM behind epilogue
        uint2 pf[8];
        if (m + 1 < NUM_M) loadA_regs(pf, homo, m + 1, N, n0, nv, wid, lane);

        // ---- epilogue on register accumulators ----
        float numr[2][2], sqr[2][2];
        #pragma unroll
        for (int mt = 0; mt < 2; ++mt)
            #pragma unroll
            for (int h = 0; h < 2; ++h) { numr[mt][h] = 0.f; sqr[mt][h] = 0.f; }

        #pragma unroll
        for (int mt = 0; mt < 2; ++mt) {
            const int rowA = wm * 32 + mt * 16 + gid;
            const int rowB = rowA + 8;
            #pragma unroll
            for (int nt = 0; nt < 4; ++nt) {
                const int col = wn * 32 + nt * 8 + tig * 2;
                float2 b2 = *reinterpret_cast<const float2*>(&sbias[col]);
                float2 tA = __bfloat1622float2(tg2[rowA * (TGT_STRIDE / 2) + (col >> 1)]);
                float2 tB = __bfloat1622float2(tg2[rowB * (TGT_STRIDE / 2) + (col >> 1)]);
                float h0 = fast_tanh(acc[mt][nt][0] + b2.x);
                float h1 = fast_tanh(acc[mt][nt][1] + b2.y);
                float h2 = fast_tanh(acc[mt][nt][2] + b2.x);
                float h3 = fast_tanh(acc[mt][nt][3] + b2.y);
                numr[mt][0] = fmaf(h0, tA.x, numr[mt][0]);
                numr[mt][0] = fmaf(h1, tA.y, numr[mt][0]);
                sqr[mt][0]  = fmaf(h0, h0, sqr[mt][0]);
                sqr[mt][0]  = fmaf(h1, h1, sqr[mt][0]);
                numr[mt][1] = fmaf(h2, tB.x, numr[mt][1]);
                numr[mt][1] = fmaf(h3, tB.y, numr[mt][1]);
                sqr[mt][1]  = fmaf(h2, h2, sqr[mt][1]);
                sqr[mt][1]  = fmaf(h3, h3, sqr[mt][1]);
            }
        }
        #pragma unroll
        for (int mt = 0; mt < 2; ++mt)
            #pragma unroll
            for (int h = 0; h < 2; ++h) {
                numr[mt][h] += __shfl_xor_sync(0xffffffffu, numr[mt][h], 1);
                numr[mt][h] += __shfl_xor_sync(0xffffffffu, numr[mt][h], 2);
                sqr[mt][h]  += __shfl_xor_sync(0xffffffffu, sqr[mt][h], 1);
                sqr[mt][h]  += __shfl_xor_sync(0xffffffffu, sqr[mt][h], 2);
            }
        if (tig == 0) {
            #pragma unroll
            for (int mt = 0; mt < 2; ++mt)
                #pragma unroll
                for (int h = 0; h < 2; ++h) {
                    int row = wm * 32 + mt * 16 + h * 8 + gid;
                    srnum[row * 8 + wn] = numr[mt][h];
                    srsq[row * 8 + wn]  = sqr[mt][h];
                }
        }
        __syncthreads();   // A reads done by all warps; reductions visible

        if (m + 1 < NUM_M) storeA(pf, smem, wid, lane);
        if (tid < BM) {
            float num = 0.f, sq = 0.f;
            #pragma unroll
            for (int w = 0; w < 8; ++w) {
                num += srnum[tid * 8 + w];
                sq  += srsq[tid * 8 + w];
            }
            float hn = fmaxf(sqrtf(sq), 1e-8f);
            slogit[m * BM + tid] = num / (hn * stn[tid]);
        }
        __syncthreads();   // new A visible; red arrays free
    }

    // ---------------- softmax over meta-paths ----------------
    if (tid < BM) {
        float mx = -1e30f;
        #pragma unroll
        for (int m = 0; m < NUM_M; ++m) mx = fmaxf(mx, slogit[m * BM + tid]);
        float e[NUM_M], sum = 0.f;
        #pragma unroll
        for (int m = 0; m < NUM_M; ++m) {
            e[m] = __expf(slogit[m * BM + tid] - mx);
            sum += e[m];
        }
        float inv = 1.f / sum;
        #pragma unroll
        for (int m = 0; m < NUM_M; ++m) slogit[m * BM + tid] = e[m] * inv;
    }
    __syncthreads();

    // ---------------- weighted sum (f32) -> out ----------------
    for (int q = tid; q < BM * (DD / 4); q += NT) {
        int r  = q >> 6;
        int c4 = q & 63;
        if (r < nv) {
            float4 o = make_float4(0.f, 0.f, 0.f, 0.f);
            #pragma unroll
            for (int m = 0; m < NUM_M; ++m) {
                float a = slogit[m * BM + r];
                float4 v = reinterpret_cast<const float4*>(homo)
                               [((size_t)m * N + n0 + r) * (DD / 4) + c4];
                o.x = fmaf(a, v.x, o.x);
                o.y = fmaf(a, v.y, o.y);
                o.z = fmaf(a, v.z, o.z);
                o.w = fmaf(a, v.w, o.w);
            }
            reinterpret_cast<float4*>(out)[(size_t)(n0 + r) * (DD / 4) + c4] = o;
        }
    }
}

extern "C" void kernel_launch(void* const* d_in, const int* in_sizes, int n_in,
                              void* d_out, int out_size) {
    const int*   nodes = (const int*)  d_in[0];
    const float* homo  = (const float*)d_in[1];
    const float* W     = (const float*)d_in[2];
    const float* b     = (const float*)d_in[3];
    const float* oe    = (const float*)d_in[4];
    float* out = (float*)d_out;
    const int N = in_sizes[0];
    (void)n_in; (void)out_size;

    cudaFuncSetAttribute(hete_mma_kernel,
                         cudaFuncAttributeMaxDynamicSharedMemorySize, SMEM_SIZE);

    int grid = (N + BM - 1) / BM;
    hete_mma_kernel<<<grid, NT, SMEM_SIZE>>>(nodes, homo, W, b, oe, out, N);
}

// round 15
// speedup vs baseline: 1.0663x; 1.0044x over previous
#include <cuda_runtime.h>
#include <cuda_bf16.h>
#include <cstdint>

#define NUM_M 8
#define DD 256
#define HH 256
#define BM 64
#define NT 512

// ---- dynamic smem layout (bytes) ----
// NOTE: tgt-gather staging occupies [OFF_A1, OFF_A1 + 33792) = A1 buffer + 1024B
// spill; OFF_BIAS starts exactly at the end of that region (R10 bug: it started
// 1024B earlier and staging clobbered bias).
#define OFF_B     0         // 4 ktiles x [256 rows x 128B] = 131072 (W bf16, resident)
#define OFF_A0    131072    // A buffer 0 (32768)
#define OFF_A1    163840    // A buffer 1 (32768); + staging spill region to 197632
#define OFF_BIAS  197632    // 256 f32
#define OFF_TN    198656    // 64 f32
#define OFF_LOGIT 198912    // 8 x 64 f32
#define OFF_PART  200960    // partials[2][64][8] float2 = 8192
#define SMEM_SIZE 209152

#define GATHER_WSTRIDE 132  // words per staged tgt row (conflict-free column reads)

#define SWZ(o) ((o) ^ (((o) >> 3) & 0x70))

__device__ __forceinline__ uint32_t smem_to_u32(const void* p) {
    uint32_t a;
    asm("{ .reg .u64 t; cvta.to.shared.u64 t, %1; cvt.u32.u64 %0, t; }" : "=r"(a) : "l"(p));
    return a;
}
__device__ __forceinline__ float fast_tanh(float x) {
    float y; asm("tanh.approx.f32 %0, %1;" : "=f"(y) : "f"(x)); return y;
}
__device__ __forceinline__ uint32_t pack_bf16x2(float lo, float hi) {
    uint32_t r; asm("cvt.rn.bf16x2.f32 %0, %1, %2;" : "=r"(r) : "f"(hi), "f"(lo)); return r;
}

#define LDSM4(r, addr) \
    asm volatile("ldmatrix.sync.aligned.m8n8.x4.shared.b16 {%0,%1,%2,%3}, [%4];" \
        : "=r"((r)[0]), "=r"((r)[1]), "=r"((r)[2]), "=r"((r)[3]) : "r"(addr))

#define MMA_BF16(c, a, bv0, bv1) \
    asm volatile("mma.sync.aligned.m16n8k16.row.col.f32.bf16.bf16.f32 " \
        "{%0,%1,%2,%3}, {%4,%5,%6,%7}, {%8,%9}, {%0,%1,%2,%3};" \
        : "+f"((c)[0]), "+f"((c)[1]), "+f"((c)[2]), "+f"((c)[3]) \
        : "r"((a)[0]), "r"((a)[1]), "r"((a)[2]), "r"((a)[3]), "r"(bv0), "r"(bv1))

// ---- linear-granule A prefetch: granule g = wid*256 + j*32 + lane ----
__device__ __forceinline__ void loadA_regs(uint2* pf, const float* __restrict__ homo,
                                           int m, int N, int n0, int nv,
                                           int wid, int lane) {
    const float4* base = reinterpret_cast<const float4*>(homo)
                         + ((size_t)m * N + n0) * (DD / 4);
    const int g0 = wid * 256 + lane;
    #pragma unroll
    for (int j = 0; j < 8; ++j) {
        int g = g0 + j * 32;
        float4 v = make_float4(0.f, 0.f, 0.f, 0.f);
        if ((g >> 6) < nv) v = base[g];
        pf[j].x = pack_bf16x2(v.x, v.y);
        pf[j].y = pack_bf16x2(v.z, v.w);
    }
}

__device__ __forceinline__ void storeA(const uint2* pf, char* smem, int bufoff,
                                       int wid, int lane) {
    const int g0 = wid * 256 + lane;
    #pragma unroll
    for (int j = 0; j < 8; ++j) {
        int g    = g0 + j * 32;
        int row  = g >> 6;
        int c4   = g & 63;
        int kt   = c4 >> 4;
        uint32_t off = SWZ((uint32_t)(row * 128 + (c4 & 15) * 8));
        *reinterpret_cast<uint2*>(smem + bufoff + kt * 8192 + off) = pf[j];
    }
}

__global__ __launch_bounds__(NT, 1)
void hete_mma_kernel(const int*   __restrict__ nodes,
                     const float* __restrict__ homo,   // [M, N, D] f32
                     const float* __restrict__ W,      // [H, D] f32
                     const float* __restrict__ bvec,   // [H]
                     const float* __restrict__ oe,     // [NODE_NUM, H]
                     float*       __restrict__ out,    // [N, D]
                     int N)
{
    extern __shared__ char smem[];
    const uint32_t sb = smem_to_u32(smem);
    const int tid  = threadIdx.x;
    const int lane = tid & 31;
    const int wid  = tid >> 5;
    const int wm   = wid & 1;    // warp row group: rows wm*32 .. +31
    const int wn   = wid >> 1;   // warp col group: cols wn*32 .. +31
    const int n0   = blockIdx.x * BM;
    const int nv   = min(BM, N - n0);

    float*  sbias  = (float*)(smem + OFF_BIAS);
    float*  stn    = (float*)(smem + OFF_TN);
    float*  slogit = (float*)(smem + OFF_LOGIT);
    float2* spart  = (float2*)(smem + OFF_PART);   // [2][64][8]
    uint32_t* gat  = (uint32_t*)(smem + OFF_A1);   // gather staging (pre-loop only)

    const int gid = lane >> 2;
    const int tig = lane & 3;

    // ---------------- init phase ----------------
    if (tid < HH) sbias[tid] = bvec[tid];   // staging no longer overlaps bias

    // gather tgt rows -> bf16 into staging (A1 + spill region), word stride 132
    for (int q = tid; q < BM * (HH / 4); q += NT) {
        int r  = q >> 6;
        int c4 = q & 63;
        int rr = (r < nv) ? r : (nv - 1);
        int row = nodes[n0 + rr];
        float4 v = reinterpret_cast<const float4*>(oe)[(size_t)row * (HH / 4) + c4];
        gat[r * GATHER_WSTRIDE + c4 * 2]     = pack_bf16x2(v.x, v.y);
        gat[r * GATHER_WSTRIDE + c4 * 2 + 1] = pack_bf16x2(v.z, v.w);
    }

    // W -> bf16 resident B: 4 k-tile blocks of [256 rows x 128B], SW128 swizzle
    for (int q = tid; q < HH * (DD / 4); q += NT) {
        int h  = q >> 6;
        int c4 = q & 63;
        float4 v = reinterpret_cast<const float4*>(W)[(size_t)h * (DD / 4) + c4];
        int ktile = c4 >> 4;
        uint32_t off = SWZ((uint32_t)(h * 128 + (c4 & 15) * 8));
        uint2 p;
        p.x = pack_bf16x2(v.x, v.y);
        p.y = pack_bf16x2(v.z, v.w);
        *reinterpret_cast<uint2*>(smem + OFF_B + ktile * 32768 + off) = p;
    }

    // prefetch A[0] while gather/W-convert settle
    uint2 pf[8];
    loadA_regs(pf, homo, 0, N, n0, nv, wid, lane);
    __syncthreads();   // staging + B + bias visible

    // tn from staged tgt (2 threads per row)
    if (tid < 2 * BM) {
        int r = tid >> 1, part = tid & 1;
        const __nv_bfloat162* trow =
            reinterpret_cast<const __nv_bfloat162*>(gat + r * GATHER_WSTRIDE) + part * 64;
        float acc = 0.f;
        #pragma unroll 16
        for (int c = 0; c < 64; ++c) {
            float2 t = __bfloat1622float2(trow[c]);
            acc = fmaf(t.x, t.x, acc);
            acc = fmaf(t.y, t.y, acc);
        }
        acc += __shfl_xor_sync(0xffffffffu, acc, 1);
        if (part == 0) stn[r] = fmaxf(sqrtf(acc), 1e-8f);
    }

    // each thread's fixed tgt operands (16 regs), read from staging
    uint32_t tgtreg[16];
    #pragma unroll
    for (int mt = 0; mt < 2; ++mt)
        #pragma unroll
        for (int h = 0; h < 2; ++h) {
            int row = wm * 32 + mt * 16 + h * 8 + gid;
            #pragma unroll
            for (int nt = 0; nt < 4; ++nt) {
                int cw = (wn * 32 + nt * 8 + tig * 2) >> 1;
                tgtreg[mt * 8 + h * 4 + nt] = gat[row * GATHER_WSTRIDE + cw];
            }
        }
    // A[0] -> buf0 (staging lives in A1; no conflict)
    storeA(pf, smem, OFF_A0, wid, lane);
    __syncthreads();   // buf0 visible; staging reads done (A1 free from m=0's storeA on)

    const int rowsel = lane & 15;
    const uint32_t kbsel = (uint32_t)((lane >> 4) << 4);
    uint32_t aOff[2], bOff[2];
    #pragma unroll
    for (int mt = 0; mt < 2; ++mt)
        aOff[mt] = (uint32_t)((wm * 32 + mt * 16 + rowsel) * 128);
    #pragma unroll
    for (int np = 0; np < 2; ++np)
        bOff[np] = (uint32_t)((wn * 32 + np * 16 + rowsel) * 128);

    // ---------------- meta-path loop: ONE barrier per m ----------------
    for (int m = 0; m < NUM_M; ++m) {
        const int cur = m & 1;
        const uint32_t aBuf = sb + (cur ? OFF_A1 : OFF_A0);

        float acc[2][4][4];
        #pragma unroll
        for (int mt = 0; mt < 2; ++mt)
            #pragma unroll
            for (int nt = 0; nt < 4; ++nt)
                #pragma unroll
                for (int e = 0; e < 4; ++e) acc[mt][nt][e] = 0.f;

        // register double-buffered LDSM pipeline over 16 k-steps
        uint32_t a[2][2][4], b[2][2][4];
        {
            #pragma unroll
            for (int mt = 0; mt < 2; ++mt) LDSM4(a[0][mt], aBuf + SWZ(aOff[mt] + kbsel));
            #pragma unroll
            for (int np = 0; np < 2; ++np) LDSM4(b[0][np], sb + OFF_B + SWZ(bOff[np] + kbsel));
        }
        #pragma unroll
        for (int ks = 0; ks < 16; ++ks) {
            const int c2 = ks & 1;
            if (ks < 15) {
                const int nks = ks + 1;
                const uint32_t kb = (uint32_t)((nks & 3) * 32) + kbsel;
                const uint32_t aB = aBuf + (nks >> 2) * 8192;
                const uint32_t bB = sb + OFF_B + (nks >> 2) * 32768;
                #pragma unroll
                for (int mt = 0; mt < 2; ++mt) LDSM4(a[nks & 1][mt], aB + SWZ(aOff[mt] + kb));
                #pragma unroll
                for (int np = 0; np < 2; ++np) LDSM4(b[nks & 1][np], bB + SWZ(bOff[np] + kb));
            }
            #pragma unroll
            for (int mt = 0; mt < 2; ++mt)
                #pragma unroll
                for (int nt = 0; nt < 4; ++nt) {
                    const int np = nt >> 1, hl = nt & 1;
                    MMA_BF16(acc[mt][nt], a[c2][mt], b[c2][np][hl], b[c2][np][hl + 2]);
                }
        }

        // prefetch A[m+1] (DRAM latency hides behind epilogue)
        if (m + 1 < NUM_M) loadA_regs(pf, homo, m + 1, N, n0, nv, wid, lane);

        // ---- epilogue: bias + tanh + dot(tgt regs) + sqnorm ----
        float numr[2][2], sqr[2][2];
        #pragma unroll
        for (int mt = 0; mt < 2; ++mt)
            #pragma unroll
            for (int h = 0; h < 2; ++h) { numr[mt][h] = 0.f; sqr[mt][h] = 0.f; }

        #pragma unroll
        for (int mt = 0; mt < 2; ++mt)
            #pragma unroll
            for (int nt = 0; nt < 4; ++nt) {
                const int col = wn * 32 + nt * 8 + tig * 2;
                float2 b2 = *reinterpret_cast<const float2*>(&sbias[col]);
                float2 tA = __bfloat1622float2(
                    *reinterpret_cast<__nv_bfloat162*>(&tgtreg[mt * 8 + nt]));
                float2 tB = __bfloat1622float2(
                    *reinterpret_cast<__nv_bfloat162*>(&tgtreg[mt * 8 + 4 + nt]));
                float h0 = fast_tanh(acc[mt][nt][0] + b2.x);
                float h1 = fast_tanh(acc[mt][nt][1] + b2.y);
                float h2 = fast_tanh(acc[mt][nt][2] + b2.x);
                float h3 = fast_tanh(acc[mt][nt][3] + b2.y);
                numr[mt][0] = fmaf(h0, tA.x, numr[mt][0]);
                numr[mt][0] = fmaf(h1, tA.y, numr[mt][0]);
                sqr[mt][0]  = fmaf(h0, h0, sqr[mt][0]);
                sqr[mt][0]  = fmaf(h1, h1, sqr[mt][0]);
                numr[mt][1] = fmaf(h2, tB.x, numr[mt][1]);
                numr[mt][1] = fmaf(h3, tB.y, numr[mt][1]);
                sqr[mt][1]  = fmaf(h2, h2, sqr[mt][1]);
                sqr[mt][1]  = fmaf(h3, h3, sqr[mt][1]);
            }
        #pragma unroll
        for (int mt = 0; mt < 2; ++mt)
            #pragma unroll
            for (int h = 0; h < 2; ++h) {
                numr[mt][h] += __shfl_xor_sync(0xffffffffu, numr[mt][h], 1);
                numr[mt][h] += __shfl_xor_sync(0xffffffffu, numr[mt][h], 2);
                sqr[mt][h]  += __shfl_xor_sync(0xffffffffu, sqr[mt][h], 1);
                sqr[mt][h]  += __shfl_xor_sync(0xffffffffu, sqr[mt][h], 2);
            }
        if (tig == 0) {
            float2* pp = spart + cur * (BM * 8);
            #pragma unroll
            for (int mt = 0; mt < 2; ++mt)
                #pragma unroll
                for (int h = 0; h < 2; ++h) {
                    int row = wm * 32 + mt * 16 + h * 8 + gid;
                    pp[row * 8 + wn] = make_float2(numr[mt][h], sqr[mt][h]);
                }
        }

        // store A[m+1] into the OTHER buffer: unread between bar(m-1) and bar(m)
        if (m + 1 < NUM_M)
            storeA(pf, smem, ((m + 1) & 1) ? OFF_A1 : OFF_A0, wid, lane);

        __syncthreads();   // bar(m): partials[cur] + A[m+1] visible; GEMM(m) reads done

        // tail: warps 0-1 compute logits while others proceed into GEMM(m+1).
        // partials[cur] next written at epilogue(m+2), which is after bar(m+1),
        // which requires these warps to have finished this read. Safe.
        if (tid < BM) {
            const float2* pp = spart + cur * (BM * 8);
            float num = 0.f, sq = 0.f;
            #pragma unroll
            for (int w = 0; w < 8; ++w) {
                float2 p = pp[tid * 8 + w];
                num += p.x; sq += p.y;
            }
            float hn = fmaxf(sqrtf(sq), 1e-8f);
            slogit[m * BM + tid] = num / (hn * stn[tid]);
        }
    }
    __syncthreads();   // all logits visible

    // ---------------- softmax over meta-paths ----------------
    if (tid < BM) {
        float mx = -1e30f;
        #pragma unroll
        for (int m = 0; m < NUM_M; ++m) mx = fmaxf(mx, slogit[m * BM + tid]);
        float e[NUM_M], sum = 0.f;
        #pragma unroll
        for (int m = 0; m < NUM_M; ++m) {
            e[m] = __expf(slogit[m * BM + tid] - mx);
            sum += e[m];
        }
        float inv = 1.f / sum;
        #pragma unroll
        for (int m = 0; m < NUM_M; ++m) slogit[m * BM + tid] = e[m] * inv;
    }
    __syncthreads();

    // ---------------- weighted sum (f32) -> out ----------------
    for (int q = tid; q < BM * (DD / 4); q += NT) {
        int r  = q >> 6;
        int c4 = q & 63;
        if (r < nv) {
            float4 o = make_float4(0.f, 0.f, 0.f, 0.f);
            #pragma unroll
            for (int m = 0; m < NUM_M; ++m) {
                float a = slogit[m * BM + r];
                float4 v = reinterpret_cast<const float4*>(homo)
                               [((size_t)m * N + n0 + r) * (DD / 4) + c4];
                o.x = fmaf(a, v.x, o.x);
                o.y = fmaf(a, v.y, o.y);
                o.z = fmaf(a, v.z, o.z);
                o.w = fmaf(a, v.w, o.w);
            }
            reinterpret_cast<float4*>(out)[(size_t)(n0 + r) * (DD / 4) + c4] = o;
        }
    }
}

extern "C" void kernel_launch(void* const* d_in, const int* in_sizes, int n_in,
                              void* d_out, int out_size) {
    const int*   nodes = (const int*)  d_in[0];
    const float* homo  = (const float*)d_in[1];
    const float* W     = (const float*)d_in[2];
    const float* b     = (const float*)d_in[3];
    const float* oe    = (const float*)d_in[4];
    float* out = (float*)d_out;
    const int N = in_sizes[0];
    (void)n_in; (void)out_size;

    cudaFuncSetAttribute(hete_mma_kernel,
                         cudaFuncAttributeMaxDynamicSharedMemorySize, SMEM_SIZE);

    int grid = (N + BM - 1) / BM;
    hete_mma_kernel<<<grid, NT, SMEM_SIZE>>>(nodes, homo, W, b, oe, out, N);
}